// round 13
// baseline (speedup 1.0000x reference)
#include <cuda_runtime.h>
#include <cuda_bf16.h>
#include <cstdint>

// out[b,c,h,w] = X[b,c,h,w] * mask_tensor[idx[b], c, h, w]
// mask is exactly {0.0f, 1.0f}, constant over (h,w) per (id,c); fixed
// channels stored as 1.0f. out = m ? X : 0 bit-exactly; m==0 channels
// (~73%) issue no X read.
//
// B=4096, C=32, HW=64. Half-batch = 1024 floats = 256 float4 = 128 v8-chunks.
//
// R13: STG.256 (st.global.v8.b32) halves store issues/L1 wavefronts, and
// each warp processes TWO half-batches with both mask gathers issued
// up-front so gather latency of tile 2 hides under tile 1's streaming.

#define NCHW     2048
#define TPB      256
#define NBLOCKS  512
#define NWARPS   (NBLOCKS * (TPB / 32))   // 4096
#define NHALF    8192                     // total half-batches

__device__ __forceinline__ void stg256(float4* p, const float4& a, const float4& b) {
    asm volatile("st.global.v8.b32 [%0], {%1,%2,%3,%4,%5,%6,%7,%8};"
        :: "l"(p),
           "r"(__float_as_uint(a.x)), "r"(__float_as_uint(a.y)),
           "r"(__float_as_uint(a.z)), "r"(__float_as_uint(a.w)),
           "r"(__float_as_uint(b.x)), "r"(__float_as_uint(b.y)),
           "r"(__float_as_uint(b.z)), "r"(__float_as_uint(b.w))
        : "memory");
}

// One half-batch: 128 v8-chunks; lane does 4 chunks (t = j*32+lane).
// Local channel of chunk t is t>>3 (8 v8-chunks per 64-float channel).
__device__ __forceinline__ void process_half(
    const float4* __restrict__ X, float4* __restrict__ out,
    int h, int lane, float mreg)
{
    const float4* Xh = X   + (size_t)h * 256;
    float4*       Oh = out + (size_t)h * 256;

    #pragma unroll
    for (int g = 0; g < 2; g++) {
        int    t[2];
        float  mm[2];
        float4 x[2][2];

        #pragma unroll
        for (int i = 0; i < 2; i++) {
            t[i]  = (g * 2 + i) * 32 + lane;                  // chunk id 0..127
            mm[i] = __shfl_sync(0xFFFFFFFFu, mreg, t[i] >> 3);
        }
        #pragma unroll
        for (int i = 0; i < 2; i++) {
            x[i][0] = make_float4(0.f, 0.f, 0.f, 0.f);
            x[i][1] = make_float4(0.f, 0.f, 0.f, 0.f);
            if (mm[i] != 0.0f) {                              // predicated, no traffic if 0
                x[i][0] = Xh[2 * t[i]];
                x[i][1] = Xh[2 * t[i] + 1];
            }
        }
        #pragma unroll
        for (int i = 0; i < 2; i++)
            stg256(&Oh[2 * t[i]], x[i][0], x[i][1]);
    }
}

__global__ void __launch_bounds__(TPB)
tied_dropout_kernel(const float4* __restrict__ X,
                    const int*    __restrict__ idx_words,
                    const float*  __restrict__ mask,
                    float4*       __restrict__ out) {
    const int tid  = threadIdx.x;
    const int lane = tid & 31;
    const int gw   = blockIdx.x * (TPB / 32) + (tid >> 5);    // 0..4095

    // ── Per-warp dtype detection (hot first 256 B of idx) ──
    // int64 LE -> odd 32-bit words all zero (ids < 60000 < 2^31);
    // int32 -> random ids, P(all 32 sampled words zero) ~ 0.
    int odd = idx_words[2 * lane + 1];
    #pragma unroll
    for (int o = 16; o; o >>= 1)
        odd |= __shfl_xor_sync(0xFFFFFFFFu, odd, o);
    const bool is64 = (odd == 0);

    // Two half-batches per warp; both gathers issued up-front so the second
    // gather's latency overlaps the first tile's streaming.
    const int h0 = gw,          b0 = h0 >> 1, half0 = h0 & 1;
    const int h1 = gw + NWARPS, b1 = h1 >> 1, half1 = h1 & 1;

    const int id0 = is64 ? idx_words[2 * b0] : idx_words[b0];
    const int id1 = is64 ? idx_words[2 * b1] : idx_words[b1];

    // Lane l holds the mask scalar for local channel (l & 15) of its half
    // (lanes 16..31 duplicate -> broadcast, free).
    const float m0 = __ldg(&mask[id0 * NCHW + ((half0 * 16 + (lane & 15)) << 6)]);
    const float m1 = __ldg(&mask[id1 * NCHW + ((half1 * 16 + (lane & 15)) << 6)]);

    process_half(X, out, h0, lane, m0);
    process_half(X, out, h1, lane, m1);
}

extern "C" void kernel_launch(void* const* d_in, const int* in_sizes, int n_in,
                              void* d_out, int out_size) {
    const float4* X         = (const float4*)d_in[0];
    const int*    idx_words = (const int*)d_in[1];
    const float*  mask      = (const float*)d_in[2];
    float4*       out       = (float4*)d_out;

    tied_dropout_kernel<<<NBLOCKS, TPB>>>(X, idx_words, mask, out);
}

// round 14
// speedup vs baseline: 1.0240x; 1.0240x over previous
#include <cuda_runtime.h>
#include <cuda_bf16.h>
#include <cstdint>

// out[b,c,h,w] = X[b,c,h,w] * mask_tensor[idx[b], c, h, w]
// mask is exactly {0.0f, 1.0f}, constant over (h,w) per (id,c); fixed
// channels stored as 1.0f. out = m ? X : 0 bit-exactly; m==0 channels
// (~73%) issue no X read.
//
// B=4096, C=32, HW=64. Half-batch = 1024 floats = 256 float4 = 128 v8-chunks.
//
// R14 = R12 (best: 8192 autonomous warps, 2 warps/batch, occ 66%) with ONE
// change: stores are STG.256 (st.global.v8.b32), halving store instruction
// count. Lane owns 4 contiguous-32B v8-chunks (t = j*32 + lane).

#define NCHW     2048
#define TPB      256                  // 8 warps = 4 batches per block
#define NBLOCKS  1024                 // 8192 half-batches / 8 warps

__device__ __forceinline__ void stg256(float4* p, const float4& a, const float4& b) {
    asm volatile("st.global.v8.b32 [%0], {%1,%2,%3,%4,%5,%6,%7,%8};"
        :: "l"(p),
           "r"(__float_as_uint(a.x)), "r"(__float_as_uint(a.y)),
           "r"(__float_as_uint(a.z)), "r"(__float_as_uint(a.w)),
           "r"(__float_as_uint(b.x)), "r"(__float_as_uint(b.y)),
           "r"(__float_as_uint(b.z)), "r"(__float_as_uint(b.w))
        : "memory");
}

__global__ void __launch_bounds__(TPB)
tied_dropout_kernel(const float4* __restrict__ X,
                    const int*    __restrict__ idx_words,
                    const float*  __restrict__ mask,
                    float4*       __restrict__ out) {
    const int tid  = threadIdx.x;
    const int lane = tid & 31;
    const int h    = blockIdx.x * 8 + (tid >> 5);   // half-batch 0..8191
    const int b    = h >> 1;                        // batch
    const int half = h & 1;                         // 16-channel half

    // ── Per-warp dtype detection (hot first 256 B of idx) ──
    // int64 LE -> odd 32-bit words all zero (ids < 60000 < 2^31);
    // int32 -> random ids, P(all 32 sampled words zero) ~ 0.
    int odd = idx_words[2 * lane + 1];
    #pragma unroll
    for (int o = 16; o; o >>= 1)
        odd |= __shfl_xor_sync(0xFFFFFFFFu, odd, o);

    const int id = (odd == 0) ? idx_words[2 * b]    // int64 (low word)
                              : idx_words[b];       // int32

    // Lane l holds the mask scalar for local channel (l & 15) of its half
    // (lanes 16..31 duplicate -> L1 broadcast, free).
    const float mreg = __ldg(&mask[id * NCHW + ((half * 16 + (lane & 15)) << 6)]);

    const float4* Xh = X   + (size_t)h * 256;
    float4*       Oh = out + (size_t)h * 256;

    // 128 v8-chunks per half; lane owns chunks t = j*32 + lane (j=0..3).
    // Local channel of chunk t is t >> 3 (8 v8-chunks per 64-float channel).
    float  m[4];
    float4 x[4][2];

    #pragma unroll
    for (int j = 0; j < 4; j++) {
        const int t = j * 32 + lane;
        m[j] = __shfl_sync(0xFFFFFFFFu, mreg, t >> 3);
    }

    // Front-batched predicated loads: m==0 lanes issue no traffic.
    #pragma unroll
    for (int j = 0; j < 4; j++) {
        const int t = j * 32 + lane;
        x[j][0] = make_float4(0.f, 0.f, 0.f, 0.f);
        x[j][1] = make_float4(0.f, 0.f, 0.f, 0.f);
        if (m[j] != 0.0f) {
            x[j][0] = Xh[2 * t];
            x[j][1] = Xh[2 * t + 1];
        }
    }

    #pragma unroll
    for (int j = 0; j < 4; j++) {
        const int t = j * 32 + lane;
        stg256(&Oh[2 * t], x[j][0], x[j][1]);       // m==1 -> X, m==0 -> 0
    }
}

extern "C" void kernel_launch(void* const* d_in, const int* in_sizes, int n_in,
                              void* d_out, int out_size) {
    const float4* X         = (const float4*)d_in[0];
    const int*    idx_words = (const int*)d_in[1];
    const float*  mask      = (const float*)d_in[2];
    float4*       out       = (float4*)d_out;

    tied_dropout_kernel<<<NBLOCKS, TPB>>>(X, idx_words, mask, out);
}

// round 15
// speedup vs baseline: 1.0267x; 1.0027x over previous
#include <cuda_runtime.h>
#include <cuda_bf16.h>
#include <cstdint>

// out[b,c,h,w] = X[b,c,h,w] * mask_tensor[idx[b], c, h, w]
// mask is exactly {0.0f, 1.0f}, constant over (h,w) per (id,c); fixed
// channels stored as 1.0f. out = m ? X : 0 bit-exactly; m==0 channels
// (~73%) issue no X read.
//
// B=4096, C=32, HW=64. Half-batch = 1024 floats = 256 float4.
//
// R15 = R12 (best: 8192 autonomous warps, 2/batch, no smem/barriers) with
// ONE change: the 8 chunk load/stores are emitted as 4 non-unrolled
// iterations of (2 loads + 2 stores) instead of one front-batched group of
// 8 LDGs. Low MLP_p1 avoids the documented cross-CTA L1tex-queue
// contention spread (spr ~2.0 at MLP_p1~8-16, oe~8 -> ~1.1 at MLP_p1~1-2);
// per-warp latency is covered by ~55 resident warps/SM.

#define NCHW     2048
#define TPB      256                  // 8 warps = 4 batches per block
#define NBLOCKS  1024                 // 8192 half-batches / 8 warps

__global__ void __launch_bounds__(TPB)
tied_dropout_kernel(const float4* __restrict__ X,
                    const int*    __restrict__ idx_words,
                    const float*  __restrict__ mask,
                    float4*       __restrict__ out) {
    const int tid  = threadIdx.x;
    const int lane = tid & 31;
    const int h    = blockIdx.x * 8 + (tid >> 5);   // half-batch 0..8191
    const int b    = h >> 1;                        // batch
    const int half = h & 1;                         // 16-channel half

    // ── Per-warp dtype detection (hot first 256 B of idx) ──
    // int64 LE -> odd 32-bit words all zero (ids < 60000 < 2^31);
    // int32 -> random ids, P(all 32 sampled words zero) ~ 0.
    int odd = idx_words[2 * lane + 1];
    #pragma unroll
    for (int o = 16; o; o >>= 1)
        odd |= __shfl_xor_sync(0xFFFFFFFFu, odd, o);

    const int id = (odd == 0) ? idx_words[2 * b]    // int64 (low word)
                              : idx_words[b];       // int32

    // Lane l holds the mask scalar for local channel (l & 15) of its half
    // (lanes 16..31 duplicate -> L1 broadcast, free).
    const float mreg = __ldg(&mask[id * NCHW + ((half * 16 + (lane & 15)) << 6)]);

    const float4* Xh = X   + (size_t)h * 256;
    float4*       Oh = out + (size_t)h * 256;

    // 8 float4 chunks/lane over the 256-float4 half; chunk j covers
    // t = j*32 + lane, local channel = t >> 4 (16 float4 per channel).
    // NOT front-batched: 4 iterations of (2 loads + 2 stores) keeps
    // MLP_p1 ~ 2 and the L1tex queue smooth across CTAs.
    #pragma unroll 1
    for (int g = 0; g < 4; g++) {
        const int t0 = (2 * g)     * 32 + lane;
        const int t1 = (2 * g + 1) * 32 + lane;

        const float m0 = __shfl_sync(0xFFFFFFFFu, mreg, t0 >> 4);
        const float m1 = __shfl_sync(0xFFFFFFFFu, mreg, t1 >> 4);

        float4 x0 = make_float4(0.f, 0.f, 0.f, 0.f);
        float4 x1 = make_float4(0.f, 0.f, 0.f, 0.f);
        if (m0 != 0.0f) x0 = Xh[t0];                // predicated: no traffic if 0
        if (m1 != 0.0f) x1 = Xh[t1];

        Oh[t0] = x0;                                // m==1 -> X, m==0 -> 0
        Oh[t1] = x1;
    }
}

extern "C" void kernel_launch(void* const* d_in, const int* in_sizes, int n_in,
                              void* d_out, int out_size) {
    const float4* X         = (const float4*)d_in[0];
    const int*    idx_words = (const int*)d_in[1];
    const float*  mask      = (const float*)d_in[2];
    float4*       out       = (float4*)d_out;

    tied_dropout_kernel<<<NBLOCKS, TPB>>>(X, idx_words, mask, out);
}

// round 16
// speedup vs baseline: 1.1743x; 1.1437x over previous
#include <cuda_runtime.h>
#include <cuda_bf16.h>
#include <cstdint>

// out[b,c,h,w] = X[b,c,h,w] * mask_tensor[idx[b], c, h, w]
// mask is exactly {0.0f, 1.0f}, constant over (h,w) per (id,c); fixed
// channels stored as 1.0f. out = m ? X : 0 bit-exactly; m==0 channels
// (~73%) issue no X read.
//
// B=4096, C=32, HW=64. Half-batch = 1024 floats = 256 float4.
//
// R16 = R12 (best: 8192 autonomous warps, 2 warps/batch, no smem, no
// barriers, front-batched predicated float4 loads, STG.128) with ONE
// change: the idx-dtype detection no longer gates the mask gather.
// Both layout interpretations (int32 / int64) are gathered speculatively
// in parallel with the shuffle-reduce; the select happens afterwards.
// Extra gather traffic (~4MB) is L2-resident broadcast — free.

#define NCHW     2048
#define TPB      256                  // 8 warps = 4 batches per block
#define NBLOCKS  1024                 // 8192 half-batches / 8 warps

__global__ void __launch_bounds__(TPB)
tied_dropout_kernel(const float4* __restrict__ X,
                    const int*    __restrict__ idx_words,
                    const float*  __restrict__ mask,
                    float4*       __restrict__ out) {
    const int tid  = threadIdx.x;
    const int lane = tid & 31;
    const int h    = blockIdx.x * 8 + (tid >> 5);   // half-batch 0..8191
    const int b    = h >> 1;                        // batch
    const int half = h & 1;                         // 16-channel half
    const int choff = (half * 16 + (lane & 15)) << 6;  // float offset of channel

    // ── Speculative id loads for BOTH layouts (independent, issue now) ──
    const int id32 = idx_words[b];                  // int32 interpretation
    const int id64 = idx_words[2 * b];              // int64 LE low word

    // ── Detection reduce runs in parallel with the gathers below ──
    // int64 LE -> odd 32-bit words all zero (ids < 60000 < 2^31);
    // int32 -> random ids, P(all 32 sampled words zero) ~ 0.
    int odd = idx_words[2 * lane + 1];

    // ── Speculative mask gathers for both interpretations ──
    // (lanes 16..31 duplicate lanes 0..15 -> L1 broadcast, free)
    const float m32 = __ldg(&mask[id32 * NCHW + choff]);
    const float m64 = __ldg(&mask[id64 * NCHW + choff]);

    #pragma unroll
    for (int o = 16; o; o >>= 1)
        odd |= __shfl_xor_sync(0xFFFFFFFFu, odd, o);

    const float mreg = (odd == 0) ? m64 : m32;

    const float4* Xh = X   + (size_t)h * 256;
    float4*       Oh = out + (size_t)h * 256;

    // 8 chunks/lane over the 256-float4 half; chunk j covers t = j*32+lane,
    // local channel = t >> 4 (16 float4 per channel).
    float  m[8];
    float4 x[8];

    #pragma unroll
    for (int j = 0; j < 8; j++) {
        const int t = j * 32 + lane;
        m[j] = __shfl_sync(0xFFFFFFFFu, mreg, t >> 4);
    }

    // Front-batched predicated loads: m==0 lanes issue no traffic.
    #pragma unroll
    for (int j = 0; j < 8; j++) {
        x[j] = make_float4(0.f, 0.f, 0.f, 0.f);
        if (m[j] != 0.0f)
            x[j] = Xh[j * 32 + lane];
    }

    #pragma unroll
    for (int j = 0; j < 8; j++)
        Oh[j * 32 + lane] = x[j];                   // m==1 -> X, m==0 -> 0
}

extern "C" void kernel_launch(void* const* d_in, const int* in_sizes, int n_in,
                              void* d_out, int out_size) {
    const float4* X         = (const float4*)d_in[0];
    const int*    idx_words = (const int*)d_in[1];
    const float*  mask      = (const float*)d_in[2];
    float4*       out       = (float4*)d_out;

    tied_dropout_kernel<<<NBLOCKS, TPB>>>(X, idx_words, mask, out);
}

// round 17
// speedup vs baseline: 1.2000x; 1.0219x over previous
#include <cuda_runtime.h>
#include <cuda_bf16.h>
#include <cstdint>

// out[b,c,h,w] = X[b,c,h,w] * mask_tensor[idx[b], c, h, w]
// mask is exactly {0.0f, 1.0f}, constant over (h,w) per (id,c); fixed
// channels stored as 1.0f. out = m ? X : 0 bit-exactly; m==0 channels
// (~73%) issue no X read.
//
// B=4096, C=32, HW=64. Quarter-batch = 512 floats = 128 float4 = 8 channels.
//
// R17 = R16 (speculative dual-layout idx/mask gathers, no smem/barriers,
// front-batched predicated float4 loads, STG.128) with ONE change:
// quarter-batch warps. 16384 one-shot warps, 4 chunks/lane: per-warp
// streaming work halves, chain-overlap population doubles, tail shrinks.

#define NCHW     2048
#define TPB      256                  // 8 warps = 2 batches per block
#define NBLOCKS  2048                 // 16384 quarter-batches / 8 warps

__global__ void __launch_bounds__(TPB)
tied_dropout_kernel(const float4* __restrict__ X,
                    const int*    __restrict__ idx_words,
                    const float*  __restrict__ mask,
                    float4*       __restrict__ out) {
    const int tid  = threadIdx.x;
    const int lane = tid & 31;
    const int q    = blockIdx.x * 8 + (tid >> 5);   // quarter-batch 0..16383
    const int b    = q >> 2;                        // batch
    const int quad = q & 3;                         // 8-channel quarter
    const int choff = (quad * 8 + (lane & 7)) << 6; // float offset of channel

    // ── Speculative id loads for BOTH layouts (independent, issue now) ──
    const int id32 = idx_words[b];                  // int32 interpretation
    const int id64 = idx_words[2 * b];              // int64 LE low word

    // ── Detection reduce runs in parallel with the gathers below ──
    // int64 LE -> odd 32-bit words all zero (ids < 60000 < 2^31);
    // int32 -> random ids, P(all 32 sampled words zero) ~ 0.
    int odd = idx_words[2 * lane + 1];

    // ── Speculative mask gathers for both interpretations ──
    // (lanes with equal lane&7 duplicate -> L1 broadcast, free)
    const float m32 = __ldg(&mask[id32 * NCHW + choff]);
    const float m64 = __ldg(&mask[id64 * NCHW + choff]);

    #pragma unroll
    for (int o = 16; o; o >>= 1)
        odd |= __shfl_xor_sync(0xFFFFFFFFu, odd, o);

    const float mreg = (odd == 0) ? m64 : m32;

    const float4* Xq = X   + (size_t)q * 128;
    float4*       Oq = out + (size_t)q * 128;

    // 4 chunks/lane over the 128-float4 quarter; chunk j covers t = j*32+lane,
    // local channel = t >> 4 (16 float4 per channel). mreg holds lane&7's
    // channel; source lane for channel ch is ch (lanes 0..7 suffice).
    float  m[4];
    float4 x[4];

    #pragma unroll
    for (int j = 0; j < 4; j++) {
        const int t = j * 32 + lane;
        m[j] = __shfl_sync(0xFFFFFFFFu, mreg, t >> 4);
    }

    // Front-batched predicated loads: m==0 lanes issue no traffic.
    #pragma unroll
    for (int j = 0; j < 4; j++) {
        x[j] = make_float4(0.f, 0.f, 0.f, 0.f);
        if (m[j] != 0.0f)
            x[j] = Xq[j * 32 + lane];
    }

    #pragma unroll
    for (int j = 0; j < 4; j++)
        Oq[j * 32 + lane] = x[j];                   // m==1 -> X, m==0 -> 0
}

extern "C" void kernel_launch(void* const* d_in, const int* in_sizes, int n_in,
                              void* d_out, int out_size) {
    const float4* X         = (const float4*)d_in[0];
    const int*    idx_words = (const int*)d_in[1];
    const float*  mask      = (const float*)d_in[2];
    float4*       out       = (float4*)d_out;

    tied_dropout_kernel<<<NBLOCKS, TPB>>>(X, idx_words, mask, out);
}